// round 3
// baseline (speedup 1.0000x reference)
#include <cuda_runtime.h>

// Fused transformer decoder block, one CTA per batch element, fp32.
// B=512, T=128, D=128, H=6, Dh=21, Dcat=126, D_FF=512.

#define NB 512
#define TT 128
#define DM 128
#define NH 6
#define DHD 21
#define DF 512
#define EPSF 1e-5f
#define SCALE 0.21821789023599236f   // 1/sqrt(21)

typedef unsigned long long u64;

__device__ __forceinline__ u64 pack2(float lo, float hi){
  u64 r; asm("mov.b64 %0,{%1,%2};" : "=l"(r) : "f"(lo), "f"(hi)); return r;
}
__device__ __forceinline__ void unpack2(u64 v, float& lo, float& hi){
  asm("mov.b64 {%0,%1},%2;" : "=f"(lo), "=f"(hi) : "l"(v));
}
__device__ __forceinline__ u64 ffma2(u64 a, u64 b, u64 c){
  u64 d; asm("fma.rn.f32x2 %0,%1,%2,%3;" : "=l"(d) : "l"(a), "l"(b), "l"(c)); return d;
}

__device__ __forceinline__ float wredsum(float v){
  #pragma unroll
  for (int o = 16; o > 0; o >>= 1) v += __shfl_xor_sync(0xffffffffu, v, o);
  return v;
}
__device__ __forceinline__ float wredmax(float v){
  #pragma unroll
  for (int o = 16; o > 0; o >>= 1) v = fmaxf(v, __shfl_xor_sync(0xffffffffu, v, o));
  return v;
}

// shared memory layout (in floats)
#define OFF_XS 0              // 128x128 : x, then x2 (residual stream)
#define OFF_HS 16384          // 128x128 : ln1(x), then ln2(x2)
#define OFF_WB 32768          // 16384 floats staging (qkv-pack + Wo slice / W1t + W2t + U)
#define OFF_QS 49152          // q,k,v: 3 * 128*21
#define SMEM_FLOATS (49152 + 3*2688)   // 57216 floats = 228864 bytes

extern "C" __global__ void __launch_bounds__(256, 1)
decoder_block_kernel(const float* __restrict__ gx,
                     const float* __restrict__ Wq,
                     const float* __restrict__ Wk,
                     const float* __restrict__ Wv,
                     const float* __restrict__ Wo,
                     const float* __restrict__ bo,
                     const float* __restrict__ W1,
                     const float* __restrict__ b1,
                     const float* __restrict__ W2,
                     const float* __restrict__ b2,
                     const float* __restrict__ g1,
                     const float* __restrict__ be1,
                     const float* __restrict__ g2,
                     const float* __restrict__ be2,
                     float* __restrict__ gout)
{
  extern __shared__ float sm[];
  float* xs = sm + OFF_XS;
  float* hs = sm + OFF_HS;
  float* wb = sm + OFF_WB;
  float* qs = sm + OFF_QS;
  float* ks = qs + 2688;
  float* vs = ks + 2688;

  const int tid  = threadIdx.x;
  const int lane = tid & 31;
  const int w    = tid >> 5;
  const int tx   = tid & 15;
  const int ty   = tid >> 4;
  const int b    = blockIdx.x;

  const float* xb = gx  + (size_t)b * (TT * DM);
  float*       ob = gout + (size_t)b * (TT * DM);

  // ---------------- load x into smem ----------------
  {
    const float4* src = (const float4*)xb;
    float4* dst = (float4*)xs;
    #pragma unroll
    for (int i = 0; i < 16; i++) dst[tid + 256 * i] = src[tid + 256 * i];
  }
  __syncthreads();

  // ---------------- LN1: hs = ln(x)*g1 + beta1 ----------------
  {
    float gv[4], bv[4];
    #pragma unroll
    for (int c = 0; c < 4; c++){ gv[c] = g1[c*32 + lane]; bv[c] = be1[c*32 + lane]; }
    for (int r = w; r < TT; r += 8){
      float v[4], s = 0.f, s2 = 0.f;
      #pragma unroll
      for (int c = 0; c < 4; c++){
        v[c] = xs[r*DM + c*32 + lane];
        s += v[c]; s2 += v[c]*v[c];
      }
      s = wredsum(s); s2 = wredsum(s2);
      float mu = s * (1.f/DM);
      float rs = rsqrtf(s2 * (1.f/DM) - mu*mu + EPSF);
      #pragma unroll
      for (int c = 0; c < 4; c++)
        hs[r*DM + c*32 + lane] = (v[c] - mu) * rs * gv[c] + bv[c];
    }
  }
  __syncthreads();

  // ---------------- attention, head by head ----------------
  float* wqkv = wb;         // 128 x 64 packed [Wq | Wk | Wv] for this head
  float* wos  = wb + 8192;  // 21 x 128 slice of Wo for this head

  for (int hh = 0; hh < NH; hh++){
    // stage packed head weights
    for (int idx = tid; idx < 2688; idx += 256){
      int d = idx / 21, e = idx % 21;
      wqkv[d*64 +      e] = Wq[hh*2688 + idx];
      wqkv[d*64 + 21 + e] = Wk[hh*2688 + idx];
      wqkv[d*64 + 42 + e] = Wv[hh*2688 + idx];
      wos[idx] = Wo[hh*21*DM + idx];
    }
    __syncthreads();

    // q|k|v = hs(128x128) @ wqkv(128x64); scatter to padded-21 buffers
    {
      u64 c2[8][2];
      #pragma unroll
      for (int i = 0; i < 8; i++){ c2[i][0] = 0ull; c2[i][1] = 0ull; }
      const int row = ty*8, col = tx*4;
      for (int k = 0; k < DM; k += 4){
        float4 a4[8];
        #pragma unroll
        for (int i = 0; i < 8; i++) a4[i] = *(const float4*)&hs[(row+i)*DM + k];
        u64 bb[4][2];
        #pragma unroll
        for (int kk = 0; kk < 4; kk++){
          float4 b4 = *(const float4*)&wqkv[(k+kk)*64 + col];
          bb[kk][0] = pack2(b4.x, b4.y); bb[kk][1] = pack2(b4.z, b4.w);
        }
        #pragma unroll
        for (int kk = 0; kk < 4; kk++){
          #pragma unroll
          for (int i = 0; i < 8; i++){
            float av = (kk==0) ? a4[i].x : (kk==1) ? a4[i].y : (kk==2) ? a4[i].z : a4[i].w;
            u64 aa = pack2(av, av);
            c2[i][0] = ffma2(aa, bb[kk][0], c2[i][0]);
            c2[i][1] = ffma2(aa, bb[kk][1], c2[i][1]);
          }
        }
      }
      #pragma unroll
      for (int i = 0; i < 8; i++){
        float f0,f1,f2,f3;
        unpack2(c2[i][0], f0, f1); unpack2(c2[i][1], f2, f3);
        float vals[4] = {f0, f1, f2, f3};
        #pragma unroll
        for (int j = 0; j < 4; j++){
          int cc = col + j;
          if (cc < 63){
            int which = cc / 21, e = cc - which * 21;
            float* dstb = (which == 0) ? qs : (which == 1) ? ks : vs;
            dstb[(row+i)*21 + e] = vals[j];
          }
        }
      }
    }
    __syncthreads();

    // warp-per-row: scores -> softmax -> AV -> fold through Wo slice into xs
    for (int t = w; t < TT; t += 8){
      float qv[21];
      #pragma unroll
      for (int e = 0; e < 21; e++) qv[e] = qs[t*21 + e];   // broadcast
      const int nb = (t >> 5) + 1;

      float s[4];
      #pragma unroll
      for (int jb = 0; jb < 4; jb++){
        s[jb] = -1e30f;
        if (jb < nb){
          int j = jb*32 + lane;
          const float* kr = &ks[j*21];
          float acc = 0.f;
          #pragma unroll
          for (int e = 0; e < 21; e++) acc += qv[e] * kr[e];
          if (j <= t) s[jb] = acc * SCALE;
        }
      }
      float m = fmaxf(fmaxf(s[0], s[1]), fmaxf(s[2], s[3]));
      m = wredmax(m);
      float p[4], psum = 0.f;
      #pragma unroll
      for (int jb = 0; jb < 4; jb++){ p[jb] = __expf(s[jb] - m); psum += p[jb]; }
      psum = wredsum(psum);
      float inv = 1.f / psum;

      float oacc[21];
      #pragma unroll
      for (int e = 0; e < 21; e++) oacc[e] = 0.f;
      #pragma unroll
      for (int jb = 0; jb < 4; jb++){
        if (jb < nb){
          int j = jb*32 + lane;
          const float* vr = &vs[j*21];
          float pj = p[jb];
          #pragma unroll
          for (int e = 0; e < 21; e++) oacc[e] += pj * vr[e];
        }
      }

      float xacc[4] = {0.f, 0.f, 0.f, 0.f};
      #pragma unroll
      for (int e = 0; e < 21; e++){
        float red = wredsum(oacc[e]) * inv;       // o[t][e], same in all lanes
        const float* wr = &wos[e*DM];
        #pragma unroll
        for (int c = 0; c < 4; c++) xacc[c] += red * wr[c*32 + lane];
      }
      #pragma unroll
      for (int c = 0; c < 4; c++) xs[t*DM + c*32 + lane] += xacc[c];
    }
    __syncthreads();
  }

  // ---------------- add bo, LN2 -> hs ----------------
  {
    float gv[4], bv[4], bov[4];
    #pragma unroll
    for (int c = 0; c < 4; c++){
      gv[c] = g2[c*32 + lane]; bv[c] = be2[c*32 + lane]; bov[c] = bo[c*32 + lane];
    }
    for (int r = w; r < TT; r += 8){
      float v[4], s = 0.f, s2 = 0.f;
      #pragma unroll
      for (int c = 0; c < 4; c++){
        v[c] = xs[r*DM + c*32 + lane] + bov[c];
        xs[r*DM + c*32 + lane] = v[c];            // xs now holds x2
        s += v[c]; s2 += v[c]*v[c];
      }
      s = wredsum(s); s2 = wredsum(s2);
      float mu = s * (1.f/DM);
      float rs = rsqrtf(s2 * (1.f/DM) - mu*mu + EPSF);
      #pragma unroll
      for (int c = 0; c < 4; c++)
        hs[r*DM + c*32 + lane] = (v[c] - mu) * rs * gv[c] + bv[c];
    }
  }
  __syncthreads();

  // ---------------- FFN: out = x2 + relu(hs@W1 + b1)@W2 + b2 ----------------
  {
    float* w1t = wb;           // 128 x 32 tile of W1
    float* w2t = wb + 4096;    // 32 x 128 tile of W2
    float* ub  = wb + 8192;    // 128 x 32 activation tile
    const int row = ty*8, col = tx*8;

    u64 cacc[8][4];
    #pragma unroll
    for (int i = 0; i < 8; i++)
      #pragma unroll
      for (int j = 0; j < 4; j++) cacc[i][j] = 0ull;

    for (int kt = 0; kt < 16; kt++){
      // stage tiles
      for (int idx = tid; idx < 4096; idx += 256){
        int d = idx >> 5, c = idx & 31;
        w1t[idx] = W1[d*DF + kt*32 + c];
        w2t[idx] = W2[kt*32*DM + idx];
      }
      __syncthreads();

      // U = relu(hs @ w1t + b1[tile]) : 128 x 32
      {
        u64 cu[8];
        #pragma unroll
        for (int i = 0; i < 8; i++) cu[i] = 0ull;
        for (int k = 0; k < DM; k += 4){
          float4 a4[8];
          #pragma unroll
          for (int i = 0; i < 8; i++) a4[i] = *(const float4*)&hs[(row+i)*DM + k];
          u64 bb[4];
          #pragma unroll
          for (int kk = 0; kk < 4; kk++){
            float2 bp = *(const float2*)&w1t[(k+kk)*32 + tx*2];
            bb[kk] = pack2(bp.x, bp.y);
          }
          #pragma unroll
          for (int kk = 0; kk < 4; kk++){
            #pragma unroll
            for (int i = 0; i < 8; i++){
              float av = (kk==0) ? a4[i].x : (kk==1) ? a4[i].y : (kk==2) ? a4[i].z : a4[i].w;
              cu[i] = ffma2(pack2(av, av), bb[kk], cu[i]);
            }
          }
        }
        float bb0 = b1[kt*32 + tx*2], bb1 = b1[kt*32 + tx*2 + 1];
        #pragma unroll
        for (int i = 0; i < 8; i++){
          float lo, hi; unpack2(cu[i], lo, hi);
          lo = fmaxf(lo + bb0, 0.f); hi = fmaxf(hi + bb1, 0.f);
          *(float2*)&ub[(row+i)*32 + tx*2] = make_float2(lo, hi);
        }
      }
      __syncthreads();

      // cacc += ub(128x32) @ w2t(32x128)
      for (int k = 0; k < 32; k += 4){
        float4 a4[8];
        #pragma unroll
        for (int i = 0; i < 8; i++) a4[i] = *(const float4*)&ub[(row+i)*32 + k];
        u64 bb[4][4];
        #pragma unroll
        for (int kk = 0; kk < 4; kk++){
          float4 x0 = *(const float4*)&w2t[(k+kk)*DM + col];
          float4 x1 = *(const float4*)&w2t[(k+kk)*DM + col + 4];
          bb[kk][0] = pack2(x0.x, x0.y); bb[kk][1] = pack2(x0.z, x0.w);
          bb[kk][2] = pack2(x1.x, x1.y); bb[kk][3] = pack2(x1.z, x1.w);
        }
        #pragma unroll
        for (int kk = 0; kk < 4; kk++){
          #pragma unroll
          for (int i = 0; i < 8; i++){
            float av = (kk==0) ? a4[i].x : (kk==1) ? a4[i].y : (kk==2) ? a4[i].z : a4[i].w;
            u64 aa = pack2(av, av);
            #pragma unroll
            for (int j = 0; j < 4; j++) cacc[i][j] = ffma2(aa, bb[kk][j], cacc[i][j]);
          }
        }
      }
      __syncthreads();
    }

    // epilogue: out = x2 + ff + b2
    float b2v[8];
    #pragma unroll
    for (int j = 0; j < 8; j++) b2v[j] = b2[col + j];
    #pragma unroll
    for (int i = 0; i < 8; i++){
      float f[8];
      #pragma unroll
      for (int j = 0; j < 4; j++) unpack2(cacc[i][j], f[2*j], f[2*j+1]);
      float4 xv0 = *(const float4*)&xs[(row+i)*DM + col];
      float4 xv1 = *(const float4*)&xs[(row+i)*DM + col + 4];
      float4 o0 = make_float4(xv0.x + f[0] + b2v[0], xv0.y + f[1] + b2v[1],
                              xv0.z + f[2] + b2v[2], xv0.w + f[3] + b2v[3]);
      float4 o1 = make_float4(xv1.x + f[4] + b2v[4], xv1.y + f[5] + b2v[5],
                              xv1.z + f[6] + b2v[6], xv1.w + f[7] + b2v[7]);
      *(float4*)&ob[(row+i)*DM + col]     = o0;
      *(float4*)&ob[(row+i)*DM + col + 4] = o1;
    }
  }
}

extern "C" void kernel_launch(void* const* d_in, const int* in_sizes, int n_in,
                              void* d_out, int out_size)
{
  (void)in_sizes; (void)n_in; (void)out_size;
  cudaFuncSetAttribute(decoder_block_kernel,
                       cudaFuncAttributeMaxDynamicSharedMemorySize,
                       SMEM_FLOATS * 4);
  decoder_block_kernel<<<NB, 256, SMEM_FLOATS * 4>>>(
      (const float*)d_in[0],  (const float*)d_in[1],  (const float*)d_in[2],
      (const float*)d_in[3],  (const float*)d_in[4],  (const float*)d_in[5],
      (const float*)d_in[6],  (const float*)d_in[7],  (const float*)d_in[8],
      (const float*)d_in[9],  (const float*)d_in[10], (const float*)d_in[11],
      (const float*)d_in[12], (const float*)d_in[13],
      (float*)d_out);
}

// round 4
// speedup vs baseline: 1.2624x; 1.2624x over previous
#include <cuda_runtime.h>

// Fused transformer decoder block, one CTA per batch element, fp32.
// B=512, T=128, D=128, H=6, Dh=21, Dcat=126, D_FF=512.
// All attention phases are register-tiled GEMMs (no warp-reduce scalar path).

#define NB 512
#define TT 128
#define DM 128
#define NH 6
#define DHD 21
#define DF 512
#define EPSF 1e-5f
#define SCALE 0.21821789023599236f   // 1/sqrt(21)

#define SS 132                        // S/P row stride (aligned float4, conflict-free)
#define QKVS 68                       // qkv staging row stride

typedef unsigned long long u64;

__device__ __forceinline__ u64 pack2(float lo, float hi){
  u64 r; asm("mov.b64 %0,{%1,%2};" : "=l"(r) : "f"(lo), "f"(hi)); return r;
}
__device__ __forceinline__ void unpack2(u64 v, float& lo, float& hi){
  asm("mov.b64 {%0,%1},%2;" : "=f"(lo), "=f"(hi) : "l"(v));
}
__device__ __forceinline__ u64 ffma2(u64 a, u64 b, u64 c){
  u64 d; asm("fma.rn.f32x2 %0,%1,%2,%3;" : "=l"(d) : "l"(a), "l"(b), "l"(c)); return d;
}
__device__ __forceinline__ float wredsum(float v){
  #pragma unroll
  for (int o = 16; o > 0; o >>= 1) v += __shfl_xor_sync(0xffffffffu, v, o);
  return v;
}
__device__ __forceinline__ float wredmax(float v){
  #pragma unroll
  for (int o = 16; o > 0; o >>= 1) v = fmaxf(v, __shfl_xor_sync(0xffffffffu, v, o));
  return v;
}

// shared memory layout (floats):
//  xs   [0      , 16384)  residual stream x / x2
//  hs   [16384  , 32768)  ln1(x) then ln2(x2)
//  wb   [32768  , 49664)  16896: S/P (128x132) | qkv_s(128x68)+wqkv(128x64) | wos | ffn tiles
//  qsm  [49664  , 52352)  q 128x21  (overlaid by O 128x24 after S computed)
//  kts  [52352  , 55040)  k^T 21x128
//  vsm  [55040  , 58112)  v 128x24 (cols 21..23 zero)
#define SMEM_FLOATS 58112   // 232448 bytes = 227 KB (sm_10x opt-in max)

extern "C" __global__ void __launch_bounds__(256, 1)
decoder_block_kernel(const float* __restrict__ gx,
                     const float* __restrict__ Wq,
                     const float* __restrict__ Wk,
                     const float* __restrict__ Wv,
                     const float* __restrict__ Wo,
                     const float* __restrict__ bo,
                     const float* __restrict__ W1,
                     const float* __restrict__ b1,
                     const float* __restrict__ W2,
                     const float* __restrict__ b2,
                     const float* __restrict__ g1,
                     const float* __restrict__ be1,
                     const float* __restrict__ g2,
                     const float* __restrict__ be2,
                     float* __restrict__ gout)
{
  extern __shared__ float sm[];
  float* xs  = sm;
  float* hs  = sm + 16384;
  float* wb  = sm + 32768;
  float* qsm = sm + 49664;
  float* kts = sm + 52352;
  float* vsm = sm + 55040;
  float* osm = qsm;              // O (128x24) overlays q (+ start of kts)

  float* qkvs = wb;              // 128 x 68 staging of [q|k|v] projection
  float* wqkv = wb + 8704;       // 128 x 64 packed weights
  float* Ssm  = wb;              // 128 x 132 scores/probs
  float* wos  = wb;              // 21 x 128 Wo slice (after O done)

  const int tid  = threadIdx.x;
  const int lane = tid & 31;
  const int w    = tid >> 5;
  const int tx   = tid & 15;
  const int ty   = tid >> 4;
  const int b    = blockIdx.x;

  const float* xb = gx   + (size_t)b * (TT * DM);
  float*       ob = gout + (size_t)b * (TT * DM);

  // ---------------- load x into smem; zero v padding ----------------
  {
    const float4* src = (const float4*)xb;
    float4* dst = (float4*)xs;
    #pragma unroll
    for (int i = 0; i < 16; i++) dst[tid + 256 * i] = src[tid + 256 * i];
    for (int idx = tid; idx < 384; idx += 256){
      int t = idx / 3, e = 21 + idx % 3;
      vsm[t*24 + e] = 0.f;
    }
  }
  __syncthreads();

  // ---------------- LN1: hs = ln(x)*g1 + beta1 ----------------
  {
    float gv[4], bv[4];
    #pragma unroll
    for (int c = 0; c < 4; c++){ gv[c] = g1[c*32 + lane]; bv[c] = be1[c*32 + lane]; }
    for (int r = w; r < TT; r += 8){
      float v[4], s = 0.f, s2 = 0.f;
      #pragma unroll
      for (int c = 0; c < 4; c++){
        v[c] = xs[r*DM + c*32 + lane];
        s += v[c]; s2 += v[c]*v[c];
      }
      s = wredsum(s); s2 = wredsum(s2);
      float mu = s * (1.f/DM);
      float rs = rsqrtf(s2 * (1.f/DM) - mu*mu + EPSF);
      #pragma unroll
      for (int c = 0; c < 4; c++)
        hs[r*DM + c*32 + lane] = (v[c] - mu) * rs * gv[c] + bv[c];
    }
  }
  __syncthreads();

  // ---------------- attention, head by head (all-GEMM) ----------------
  for (int hh = 0; hh < NH; hh++){
    // -- stage packed head weights [Wq|Wk|Wv] into wqkv (128x64) --
    for (int idx = tid; idx < 2688; idx += 256){
      int d = idx / 21, e = idx % 21;
      wqkv[d*64 +      e] = Wq[hh*2688 + idx];
      wqkv[d*64 + 21 + e] = Wk[hh*2688 + idx];
      wqkv[d*64 + 42 + e] = Wv[hh*2688 + idx];
    }
    if (tid < 128) wqkv[tid*64 + 63] = 0.f;
    __syncthreads();

    // -- qkv_s(128x68) = hs(128x128) @ wqkv(128x64) --
    {
      u64 c2[8][2];
      #pragma unroll
      for (int i = 0; i < 8; i++){ c2[i][0] = 0ull; c2[i][1] = 0ull; }
      const int row = ty*8, col = tx*4;
      for (int k = 0; k < DM; k += 4){
        float4 a4[8];
        #pragma unroll
        for (int i = 0; i < 8; i++) a4[i] = *(const float4*)&hs[(row+i)*DM + k];
        u64 bb[4][2];
        #pragma unroll
        for (int kk = 0; kk < 4; kk++){
          float4 b4 = *(const float4*)&wqkv[(k+kk)*64 + col];
          bb[kk][0] = pack2(b4.x, b4.y); bb[kk][1] = pack2(b4.z, b4.w);
        }
        #pragma unroll
        for (int kk = 0; kk < 4; kk++){
          #pragma unroll
          for (int i = 0; i < 8; i++){
            float av = (kk==0) ? a4[i].x : (kk==1) ? a4[i].y : (kk==2) ? a4[i].z : a4[i].w;
            u64 aa = pack2(av, av);
            c2[i][0] = ffma2(aa, bb[kk][0], c2[i][0]);
            c2[i][1] = ffma2(aa, bb[kk][1], c2[i][1]);
          }
        }
      }
      #pragma unroll
      for (int i = 0; i < 8; i++){
        float f0,f1,f2,f3;
        unpack2(c2[i][0], f0, f1); unpack2(c2[i][1], f2, f3);
        *(float4*)&qkvs[(row+i)*QKVS + col] = make_float4(f0,f1,f2,f3);
      }
    }
    __syncthreads();

    // -- transpose/scatter: q (scaled), k^T, v --
    for (int idx = tid; idx < 2688; idx += 256){
      int t = idx / 21, e = idx % 21;
      qsm[idx] = qkvs[t*QKVS + e] * SCALE;
    }
    for (int idx = tid; idx < 2688; idx += 256){
      int e = idx >> 7, t = idx & 127;
      kts[idx] = qkvs[t*QKVS + 21 + e];
    }
    for (int idx = tid; idx < 2688; idx += 256){
      int t = idx / 21, e = idx % 21;
      vsm[t*24 + e] = qkvs[t*QKVS + 42 + e];
    }
    __syncthreads();

    // -- S(128x128) = q @ k^T  (k = 21) --
    {
      u64 acc[8][4];
      #pragma unroll
      for (int i = 0; i < 8; i++)
        #pragma unroll
        for (int j = 0; j < 4; j++) acc[i][j] = 0ull;
      const int row = ty*8, col = tx*8;
      #pragma unroll
      for (int e = 0; e < 21; e++){
        float qv[8];
        #pragma unroll
        for (int i = 0; i < 8; i++) qv[i] = qsm[(row+i)*21 + e];
        float4 k0 = *(const float4*)&kts[e*128 + col];
        float4 k1 = *(const float4*)&kts[e*128 + col + 4];
        u64 kb[4] = { pack2(k0.x,k0.y), pack2(k0.z,k0.w),
                      pack2(k1.x,k1.y), pack2(k1.z,k1.w) };
        #pragma unroll
        for (int i = 0; i < 8; i++){
          u64 aa = pack2(qv[i], qv[i]);
          #pragma unroll
          for (int j = 0; j < 4; j++) acc[i][j] = ffma2(aa, kb[j], acc[i][j]);
        }
      }
      #pragma unroll
      for (int i = 0; i < 8; i++){
        float f[8];
        #pragma unroll
        for (int j = 0; j < 4; j++) unpack2(acc[i][j], f[2*j], f[2*j+1]);
        *(float4*)&Ssm[(row+i)*SS + col]     = make_float4(f[0],f[1],f[2],f[3]);
        *(float4*)&Ssm[(row+i)*SS + col + 4] = make_float4(f[4],f[5],f[6],f[7]);
      }
    }
    __syncthreads();

    // -- masked softmax rows (warp per row), normalize in place --
    for (int r = w; r < TT; r += 8){
      float v[4];
      #pragma unroll
      for (int kb = 0; kb < 4; kb++){
        int c = kb*32 + lane;
        float s = Ssm[r*SS + c];
        v[kb] = (c <= r) ? s : -1e30f;
      }
      float m = fmaxf(fmaxf(v[0], v[1]), fmaxf(v[2], v[3]));
      m = wredmax(m);
      float p[4], psum = 0.f;
      #pragma unroll
      for (int kb = 0; kb < 4; kb++){ p[kb] = __expf(v[kb] - m); psum += p[kb]; }
      psum = wredsum(psum);
      float inv = 1.f / psum;
      #pragma unroll
      for (int kb = 0; kb < 4; kb++){
        int c = kb*32 + lane;
        Ssm[r*SS + c] = p[kb] * inv;
      }
    }
    __syncthreads();

    // -- O(128x24) = P(128x128) @ v(128x24)  (k = 128) --
    {
      const int rg = tid >> 3, cg = tid & 7;
      const int r0 = rg*4, c0 = cg*3;
      float acc[4][3];
      #pragma unroll
      for (int i = 0; i < 4; i++)
        #pragma unroll
        for (int u = 0; u < 3; u++) acc[i][u] = 0.f;
      for (int j = 0; j < 128; j += 4){
        float4 pr[4];
        #pragma unroll
        for (int i = 0; i < 4; i++) pr[i] = *(const float4*)&Ssm[(r0+i)*SS + j];
        float vv[4][3];
        #pragma unroll
        for (int jj = 0; jj < 4; jj++)
          #pragma unroll
          for (int u = 0; u < 3; u++) vv[jj][u] = vsm[(j+jj)*24 + c0 + u];
        #pragma unroll
        for (int jj = 0; jj < 4; jj++){
          #pragma unroll
          for (int i = 0; i < 4; i++){
            float pv = (jj==0) ? pr[i].x : (jj==1) ? pr[i].y : (jj==2) ? pr[i].z : pr[i].w;
            #pragma unroll
            for (int u = 0; u < 3; u++) acc[i][u] += pv * vv[jj][u];
          }
        }
      }
      __syncthreads();   // P no longer needed; osm overlays q (not P), but sync before wos stage
      #pragma unroll
      for (int i = 0; i < 4; i++)
        #pragma unroll
        for (int u = 0; u < 3; u++) osm[(r0+i)*24 + c0 + u] = acc[i][u];
    }
    __syncthreads();

    // -- stage wos (21x128) into wb --
    for (int idx = tid; idx < 2688; idx += 256)
      wos[idx] = Wo[hh*21*DM + idx];
    __syncthreads();

    // -- xs += O(128x24,cols>=21 zero) @ wos(21x128)  (k = 21) --
    {
      u64 acc[8][4];
      #pragma unroll
      for (int i = 0; i < 8; i++)
        #pragma unroll
        for (int j = 0; j < 4; j++) acc[i][j] = 0ull;
      const int row = ty*8, col = tx*8;
      #pragma unroll
      for (int e = 0; e < 21; e++){
        float ov[8];
        #pragma unroll
        for (int i = 0; i < 8; i++) ov[i] = osm[(row+i)*24 + e];
        float4 w0 = *(const float4*)&wos[e*128 + col];
        float4 w1 = *(const float4*)&wos[e*128 + col + 4];
        u64 kb[4] = { pack2(w0.x,w0.y), pack2(w0.z,w0.w),
                      pack2(w1.x,w1.y), pack2(w1.z,w1.w) };
        #pragma unroll
        for (int i = 0; i < 8; i++){
          u64 aa = pack2(ov[i], ov[i]);
          #pragma unroll
          for (int j = 0; j < 4; j++) acc[i][j] = ffma2(aa, kb[j], acc[i][j]);
        }
      }
      #pragma unroll
      for (int i = 0; i < 8; i++){
        float f[8];
        #pragma unroll
        for (int j = 0; j < 4; j++) unpack2(acc[i][j], f[2*j], f[2*j+1]);
        float4 x0 = *(const float4*)&xs[(row+i)*DM + col];
        float4 x1 = *(const float4*)&xs[(row+i)*DM + col + 4];
        x0.x += f[0]; x0.y += f[1]; x0.z += f[2]; x0.w += f[3];
        x1.x += f[4]; x1.y += f[5]; x1.z += f[6]; x1.w += f[7];
        *(float4*)&xs[(row+i)*DM + col]     = x0;
        *(float4*)&xs[(row+i)*DM + col + 4] = x1;
      }
    }
    __syncthreads();
  }

  // ---------------- add bo, LN2 -> hs ----------------
  {
    float gv[4], bv[4], bov[4];
    #pragma unroll
    for (int c = 0; c < 4; c++){
      gv[c] = g2[c*32 + lane]; bv[c] = be2[c*32 + lane]; bov[c] = bo[c*32 + lane];
    }
    for (int r = w; r < TT; r += 8){
      float v[4], s = 0.f, s2 = 0.f;
      #pragma unroll
      for (int c = 0; c < 4; c++){
        v[c] = xs[r*DM + c*32 + lane] + bov[c];
        xs[r*DM + c*32 + lane] = v[c];            // xs now holds x2
        s += v[c]; s2 += v[c]*v[c];
      }
      s = wredsum(s); s2 = wredsum(s2);
      float mu = s * (1.f/DM);
      float rs = rsqrtf(s2 * (1.f/DM) - mu*mu + EPSF);
      #pragma unroll
      for (int c = 0; c < 4; c++)
        hs[r*DM + c*32 + lane] = (v[c] - mu) * rs * gv[c] + bv[c];
    }
  }
  __syncthreads();

  // ---------------- FFN: out = x2 + relu(hs@W1 + b1)@W2 + b2 ----------------
  {
    float* w1t = wb;           // 128 x 32 tile of W1
    float* w2t = wb + 4096;    // 32 x 128 tile of W2
    float* ub  = wb + 8192;    // 128 x 32 activation tile
    const int row = ty*8, col = tx*8;

    u64 cacc[8][4];
    #pragma unroll
    for (int i = 0; i < 8; i++)
      #pragma unroll
      for (int j = 0; j < 4; j++) cacc[i][j] = 0ull;

    for (int kt = 0; kt < 16; kt++){
      for (int idx = tid; idx < 4096; idx += 256){
        int d = idx >> 5, c = idx & 31;
        w1t[idx] = W1[d*DF + kt*32 + c];
        w2t[idx] = W2[kt*32*DM + idx];
      }
      __syncthreads();

      // U = relu(hs @ w1t + b1[tile]) : 128 x 32
      {
        u64 cu[8];
        #pragma unroll
        for (int i = 0; i < 8; i++) cu[i] = 0ull;
        for (int k = 0; k < DM; k += 4){
          float4 a4[8];
          #pragma unroll
          for (int i = 0; i < 8; i++) a4[i] = *(const float4*)&hs[(row+i)*DM + k];
          u64 bb[4];
          #pragma unroll
          for (int kk = 0; kk < 4; kk++){
            float2 bp = *(const float2*)&w1t[(k+kk)*32 + tx*2];
            bb[kk] = pack2(bp.x, bp.y);
          }
          #pragma unroll
          for (int kk = 0; kk < 4; kk++){
            #pragma unroll
            for (int i = 0; i < 8; i++){
              float av = (kk==0) ? a4[i].x : (kk==1) ? a4[i].y : (kk==2) ? a4[i].z : a4[i].w;
              cu[i] = ffma2(pack2(av, av), bb[kk], cu[i]);
            }
          }
        }
        float bb0 = b1[kt*32 + tx*2], bb1 = b1[kt*32 + tx*2 + 1];
        #pragma unroll
        for (int i = 0; i < 8; i++){
          float lo, hi; unpack2(cu[i], lo, hi);
          lo = fmaxf(lo + bb0, 0.f); hi = fmaxf(hi + bb1, 0.f);
          *(float2*)&ub[(row+i)*32 + tx*2] = make_float2(lo, hi);
        }
      }
      __syncthreads();

      // cacc += ub(128x32) @ w2t(32x128)
      for (int k = 0; k < 32; k += 4){
        float4 a4[8];
        #pragma unroll
        for (int i = 0; i < 8; i++) a4[i] = *(const float4*)&ub[(row+i)*32 + k];
        u64 bb[4][4];
        #pragma unroll
        for (int kk = 0; kk < 4; kk++){
          float4 x0 = *(const float4*)&w2t[(k+kk)*DM + col];
          float4 x1 = *(const float4*)&w2t[(k+kk)*DM + col + 4];
          bb[kk][0] = pack2(x0.x, x0.y); bb[kk][1] = pack2(x0.z, x0.w);
          bb[kk][2] = pack2(x1.x, x1.y); bb[kk][3] = pack2(x1.z, x1.w);
        }
        #pragma unroll
        for (int kk = 0; kk < 4; kk++){
          #pragma unroll
          for (int i = 0; i < 8; i++){
            float av = (kk==0) ? a4[i].x : (kk==1) ? a4[i].y : (kk==2) ? a4[i].z : a4[i].w;
            u64 aa = pack2(av, av);
            #pragma unroll
            for (int j = 0; j < 4; j++) cacc[i][j] = ffma2(aa, bb[kk][j], cacc[i][j]);
          }
        }
      }
      __syncthreads();
    }

    // epilogue: out = x2 + ff + b2
    float b2v[8];
    #pragma unroll
    for (int j = 0; j < 8; j++) b2v[j] = b2[col + j];
    #pragma unroll
    for (int i = 0; i < 8; i++){
      float f[8];
      #pragma unroll
      for (int j = 0; j < 4; j++) unpack2(cacc[i][j], f[2*j], f[2*j+1]);
      float4 xv0 = *(const float4*)&xs[(row+i)*DM + col];
      float4 xv1 = *(const float4*)&xs[(row+i)*DM + col + 4];
      float4 o0 = make_float4(xv0.x + f[0] + b2v[0], xv0.y + f[1] + b2v[1],
                              xv0.z + f[2] + b2v[2], xv0.w + f[3] + b2v[3]);
      float4 o1 = make_float4(xv1.x + f[4] + b2v[4], xv1.y + f[5] + b2v[5],
                              xv1.z + f[6] + b2v[6], xv1.w + f[7] + b2v[7]);
      *(float4*)&ob[(row+i)*DM + col]     = o0;
      *(float4*)&ob[(row+i)*DM + col + 4] = o1;
    }
  }
}

extern "C" void kernel_launch(void* const* d_in, const int* in_sizes, int n_in,
                              void* d_out, int out_size)
{
  (void)in_sizes; (void)n_in; (void)out_size;
  cudaFuncSetAttribute(decoder_block_kernel,
                       cudaFuncAttributeMaxDynamicSharedMemorySize,
                       SMEM_FLOATS * 4);
  decoder_block_kernel<<<NB, 256, SMEM_FLOATS * 4>>>(
      (const float*)d_in[0],  (const float*)d_in[1],  (const float*)d_in[2],
      (const float*)d_in[3],  (const float*)d_in[4],  (const float*)d_in[5],
      (const float*)d_in[6],  (const float*)d_in[7],  (const float*)d_in[8],
      (const float*)d_in[9],  (const float*)d_in[10], (const float*)d_in[11],
      (const float*)d_in[12], (const float*)d_in[13],
      (float*)d_out);
}